// round 1
// baseline (speedup 1.0000x reference)
#include <cuda_runtime.h>

// Problem constants
#define NN   1024
#define PP   4
#define SS   12
#define MM   64
#define KK   16
#define LL   8
#define MK   80
#define NSYM 13           // S+1 symbols (pilot + payload)

// Flattened output layout: [info_pilot | info_sig | H_true | noise_pwr]
#define IP_OFF 0
#define IS_OFF (NN*PP*MM*2)                  //   524288
#define HT_OFF (IS_OFF + NN*PP*SS*MM*2)      //  6815744
#define NP_OFF (HT_OFF + NN*PP*MM*2)         //  7340032

#define NOISE_PWR 1.5625e-4f                 // 1/(64*10^2)
// sqrt(noise_pwr/2)
#define CNOISE 8.8388347648e-3f

__device__ __forceinline__ float2 cmul(float2 a, float2 b) {
    return make_float2(a.x*b.x - a.y*b.y, a.x*b.y + a.y*b.x);
}
__device__ __forceinline__ void cmac(float2& acc, float2 a, float2 b) {
    acc.x = fmaf(a.x, b.x, fmaf(-a.y, b.y, acc.x));
    acc.y = fmaf(a.x, b.y, fmaf( a.y, b.x, acc.y));
}

__global__ __launch_bounds__(128) void ofdm_kernel(
    const float* __restrict__ x,          // (N,P,S,M,2)
    const float* __restrict__ pilot_raw,  // (N,P,1,M,2)
    const float* __restrict__ cof_unit,   // (N,P,L,2)
    const float* __restrict__ noise_unit, // (N,P,S+1,MK,2)
    float* __restrict__ out)
{
    __shared__ float2 Wtab[64];          // W64^j = exp(-2*pi*i*j/64)
    __shared__ float2 Hs[64];
    __shared__ float2 cofs[8];
    __shared__ float2 Z[NSYM][8][9];     // padded transpose buffer
    __shared__ float  warpsum[4];
    __shared__ float  alpha_s;

    const int blk = blockIdx.x;          // n*P + p  (0..4095)
    const int tid = threadIdx.x;

    // ---- twiddle table ----
    if (tid < 64) {
        float s, c;
        sincosf(-6.283185307179586f * (float)tid * (1.0f/64.0f), &s, &c);
        Wtab[tid] = make_float2(c, s);
    }
    // ---- channel taps: cof[l] = sqrt(prof[l]/2) * cof_unit ----
    if (tid < 8) {
        float prof = expf(-0.25f * (float)tid);
        float psum = (1.0f - expf(-2.0f)) / (1.0f - expf(-0.25f));
        float amp  = sqrtf(0.5f * prof / psum);
        float2 cu  = ((const float2*)cof_unit)[blk * 8 + tid];
        cofs[tid]  = make_float2(amp * cu.x, amp * cu.y);
    }
    // ---- pilot power: mean over 128 floats ----
    {
        float v  = pilot_raw[blk * 128 + tid];
        float p2 = v * v;
        #pragma unroll
        for (int o = 16; o; o >>= 1) p2 += __shfl_down_sync(0xffffffffu, p2, o);
        if ((tid & 31) == 0) warpsum[tid >> 5] = p2;
    }
    __syncthreads();
    if (tid == 0) {
        float s = warpsum[0] + warpsum[1] + warpsum[2] + warpsum[3];
        alpha_s = sqrtf(0.5f * 128.0f / s);   // sqrt(PWR/2)/sqrt(mean)
    }

    // ---- H_true[m] = sum_l cof[l] * W64^{l*m} (only 8 taps) ----
    if (tid < 64) {
        float2 h = make_float2(0.f, 0.f);
        #pragma unroll
        for (int l = 0; l < 8; l++)
            cmac(h, cofs[l], Wtab[(l * tid) & 63]);
        Hs[tid] = h;
        ((float2*)(out + HT_OFF))[blk * 64 + tid] = h;
    }

    // ---- noise FFT64 stage 1: 8 threads per symbol, thread b handles
    //      residue class t = 8a+b; merged twiddle: z[b][c] = sum_a n[8a+b]*W64^{(8a+b)c}
    const int sym = tid >> 3;
    const int lb  = tid & 7;
    if (tid < 8 * NSYM) {
        const float2* nb = (const float2*)noise_unit
                         + (size_t)blk * NSYM * MK + sym * MK + KK + lb;
        float2 in[8];
        #pragma unroll
        for (int a = 0; a < 8; a++) in[a] = nb[a * 8];

        #pragma unroll
        for (int c = 0; c < 8; c++) {
            float2 acc = make_float2(0.f, 0.f);
            int bc = (lb * c) & 63;
            #pragma unroll
            for (int a = 0; a < 8; a++)
                cmac(acc, in[a], Wtab[(8*a*c + bc) & 63]);
            Z[sym][lb][c] = acc;
        }
    }
    __syncthreads();

    // ---- stage 2 + fused epilogue: thread (sym, c) produces m = c + 8d ----
    if (tid < 8 * NSYM) {
        const int c = lb;
        float2 z[8];
        #pragma unroll
        for (int b = 0; b < 8; b++) z[b] = Z[sym][b][c];

        float2 NF[8];
        #pragma unroll
        for (int d = 0; d < 8; d++) {
            float2 acc = make_float2(0.f, 0.f);
            #pragma unroll
            for (int b = 0; b < 8; b++)
                cmac(acc, z[b], Wtab[(8 * b * d) & 63]);   // W8^{bd}
            NF[d] = acc;
        }

        if (sym == 0) {
            // info_pilot = H * (alpha * pilot) + CNOISE * NF
            const float2* pr = (const float2*)pilot_raw + blk * 64;
            float2* o = (float2*)(out + IP_OFF) + blk * 64;
            const float a_ = alpha_s;
            #pragma unroll
            for (int d = 0; d < 8; d++) {
                int m = c + 8 * d;
                float2 s = pr[m];
                s.x *= a_; s.y *= a_;
                float2 r = cmul(Hs[m], s);
                r.x = fmaf(CNOISE, NF[d].x, r.x);
                r.y = fmaf(CNOISE, NF[d].y, r.y);
                o[m] = r;
            }
        } else {
            // info_sig = H * X + CNOISE * NF
            const float2* xs = (const float2*)x + ((size_t)blk * SS + (sym - 1)) * 64;
            float2* o = (float2*)(out + IS_OFF) + ((size_t)blk * SS + (sym - 1)) * 64;
            #pragma unroll
            for (int d = 0; d < 8; d++) {
                int m = c + 8 * d;
                float2 r = cmul(Hs[m], xs[m]);
                r.x = fmaf(CNOISE, NF[d].x, r.x);
                r.y = fmaf(CNOISE, NF[d].y, r.y);
                o[m] = r;
            }
        }
    }

    if (blk == 0 && tid == 0) out[NP_OFF] = NOISE_PWR;
}

extern "C" void kernel_launch(void* const* d_in, const int* in_sizes, int n_in,
                              void* d_out, int out_size) {
    const float* x          = (const float*)d_in[0];
    const float* pilot_raw  = (const float*)d_in[1];
    const float* cof_unit   = (const float*)d_in[2];
    const float* noise_unit = (const float*)d_in[3];
    float* out = (float*)d_out;

    ofdm_kernel<<<NN * PP, 128>>>(x, pilot_raw, cof_unit, noise_unit, out);
}

// round 2
// speedup vs baseline: 1.2137x; 1.2137x over previous
#include <cuda_runtime.h>

// Problem constants
#define NN   1024
#define PP   4
#define SS   12
#define MM   64
#define KK   16
#define MK   80
#define NSYM 13
#define NBLK (NN*PP)              // 4096
#define NSYMTOT (NBLK*NSYM)       // 53248

// Output layout: [info_pilot | info_sig | H_true | noise_pwr]
#define IP_OFF 0
#define IS_OFF (NN*PP*MM*2)                  //   524288
#define HT_OFF (IS_OFF + NN*PP*SS*MM*2)      //  6815744
#define NP_OFF (HT_OFF + NN*PP*MM*2)         //  7340032

#define NOISE_PWR 1.5625e-4f                 // 1/(64*10^2)
#define CNOISE 8.8388347648e-3f              // sqrt(noise_pwr/2)
#define SQ2H 0.70710678f

// W64^k = exp(-2*pi*i*k/64) = (cos, -sin)
__device__ const float2 g_W64[64] = {
    { 1.00000000f,  0.00000000f}, { 0.99518473f, -0.09801714f},
    { 0.98078528f, -0.19509032f}, { 0.95694034f, -0.29028468f},
    { 0.92387953f, -0.38268343f}, { 0.88192126f, -0.47139674f},
    { 0.83146961f, -0.55557023f}, { 0.77301045f, -0.63439328f},
    { 0.70710678f, -0.70710678f}, { 0.63439328f, -0.77301045f},
    { 0.55557023f, -0.83146961f}, { 0.47139674f, -0.88192126f},
    { 0.38268343f, -0.92387953f}, { 0.29028468f, -0.95694034f},
    { 0.19509032f, -0.98078528f}, { 0.09801714f, -0.99518473f},
    { 0.00000000f, -1.00000000f}, {-0.09801714f, -0.99518473f},
    {-0.19509032f, -0.98078528f}, {-0.29028468f, -0.95694034f},
    {-0.38268343f, -0.92387953f}, {-0.47139674f, -0.88192126f},
    {-0.55557023f, -0.83146961f}, {-0.63439328f, -0.77301045f},
    {-0.70710678f, -0.70710678f}, {-0.77301045f, -0.63439328f},
    {-0.83146961f, -0.55557023f}, {-0.88192126f, -0.47139674f},
    {-0.92387953f, -0.38268343f}, {-0.95694034f, -0.29028468f},
    {-0.98078528f, -0.19509032f}, {-0.99518473f, -0.09801714f},
    {-1.00000000f,  0.00000000f}, {-0.99518473f,  0.09801714f},
    {-0.98078528f,  0.19509032f}, {-0.95694034f,  0.29028468f},
    {-0.92387953f,  0.38268343f}, {-0.88192126f,  0.47139674f},
    {-0.83146961f,  0.55557023f}, {-0.77301045f,  0.63439328f},
    {-0.70710678f,  0.70710678f}, {-0.63439328f,  0.77301045f},
    {-0.55557023f,  0.83146961f}, {-0.47139674f,  0.88192126f},
    {-0.38268343f,  0.92387953f}, {-0.29028468f,  0.95694034f},
    {-0.19509032f,  0.98078528f}, {-0.09801714f,  0.99518473f},
    { 0.00000000f,  1.00000000f}, { 0.09801714f,  0.99518473f},
    { 0.19509032f,  0.98078528f}, { 0.29028468f,  0.95694034f},
    { 0.38268343f,  0.92387953f}, { 0.47139674f,  0.88192126f},
    { 0.55557023f,  0.83146961f}, { 0.63439328f,  0.77301045f},
    { 0.70710678f,  0.70710678f}, { 0.77301045f,  0.63439328f},
    { 0.83146961f,  0.55557023f}, { 0.88192126f,  0.47139674f},
    { 0.92387953f,  0.38268343f}, { 0.95694034f,  0.29028468f},
    { 0.98078528f,  0.19509032f}, { 0.99518473f,  0.09801714f}
};

__device__ __forceinline__ float2 cadd(float2 a, float2 b) { return make_float2(a.x+b.x, a.y+b.y); }
__device__ __forceinline__ float2 csub(float2 a, float2 b) { return make_float2(a.x-b.x, a.y-b.y); }
__device__ __forceinline__ float2 mul_mi(float2 z) { return make_float2(z.y, -z.x); }   // -i*z
__device__ __forceinline__ float2 cmul(float2 a, float2 b) {
    return make_float2(a.x*b.x - a.y*b.y, a.x*b.y + a.y*b.x);
}
__device__ __forceinline__ void cmac(float2& acc, float2 a, float2 b) {
    acc.x = fmaf(a.x, b.x, fmaf(-a.y, b.y, acc.x));
    acc.y = fmaf(a.x, b.y, fmaf( a.y, b.x, acc.y));
}
// W8^1 * z = (s(x+y), s(y-x)),  W8^3 * z = (s(y-x), -s(x+y)),  s = sqrt(2)/2
__device__ __forceinline__ float2 w81(float2 z) { return make_float2(SQ2H*(z.x+z.y), SQ2H*(z.y-z.x)); }
__device__ __forceinline__ float2 w83(float2 z) { return make_float2(SQ2H*(z.y-z.x), -SQ2H*(z.x+z.y)); }

// X[k] = sum_n x[n] * W8^{nk}  (fast radix-2 DIT)
__device__ __forceinline__ void dft8(const float2* x, float2* X) {
    float2 t0 = cadd(x[0], x[4]), t1 = csub(x[0], x[4]);
    float2 t2 = cadd(x[2], x[6]), t3 = csub(x[2], x[6]);
    float2 E0 = cadd(t0, t2), E2 = csub(t0, t2);
    float2 mt3 = mul_mi(t3);
    float2 E1 = cadd(t1, mt3), E3 = csub(t1, mt3);

    float2 s0 = cadd(x[1], x[5]), s1 = csub(x[1], x[5]);
    float2 s2 = cadd(x[3], x[7]), s3 = csub(x[3], x[7]);
    float2 O0 = cadd(s0, s2), O2 = csub(s0, s2);
    float2 ms3 = mul_mi(s3);
    float2 O1 = cadd(s1, ms3), O3 = csub(s1, ms3);

    float2 o1 = w81(O1);
    float2 o2 = mul_mi(O2);
    float2 o3 = w83(O3);

    X[0] = cadd(E0, O0); X[4] = csub(E0, O0);
    X[1] = cadd(E1, o1); X[5] = csub(E1, o1);
    X[2] = cadd(E2, o2); X[6] = csub(E2, o2);
    X[3] = cadd(E3, o3); X[7] = csub(E3, o3);
}

// ---- K1: H_true = FFT64 of zero-padded channel taps (8 taps) ----
__global__ __launch_bounds__(256) void ofdm_k1(const float* __restrict__ cof_unit,
                                               float* __restrict__ out)
{
    int g = blockIdx.x * 256 + threadIdx.x;   // 0..262143
    int blk = g >> 6;
    int m = g & 63;

    float psum = (1.0f - expf(-2.0f)) / (1.0f - expf(-0.25f));
    const float2* cu = (const float2*)cof_unit + blk * 8;

    float2 h = make_float2(0.f, 0.f);
    #pragma unroll
    for (int l = 0; l < 8; l++) {
        float amp = sqrtf(0.5f * expf(-0.25f * (float)l) / psum);
        float2 c = cu[l];
        float2 cf = make_float2(amp * c.x, amp * c.y);
        cmac(h, cf, g_W64[(l * m) & 63]);
    }
    ((float2*)(out + HT_OFF))[g] = h;
    if (g == 0) out[NP_OFF] = NOISE_PWR;
}

// ---- K2: per-symbol noise FFT64 + fused H*X + noise epilogue ----
__global__ __launch_bounds__(256) void ofdm_k2(
    const float* __restrict__ x,
    const float* __restrict__ pilot_raw,
    const float* __restrict__ noise_unit,
    float* __restrict__ out)
{
    __shared__ float2 sW[64];
    const int tid = threadIdx.x;
    if (tid < 64) sW[tid] = g_W64[tid];
    __syncthreads();

    const int gsym = (blockIdx.x * 256 + tid) >> 3;   // 0..53247
    const int lb = tid & 7;
    const int blk = gsym / NSYM;
    const int sym = gsym - blk * NSYM;
    const bool isp = (sym == 0);

    // ---- issue all global loads up front (MLP) ----
    const float2* nb = (const float2*)noise_unit
                     + (size_t)blk * NSYM * MK + sym * MK + KK + lb;
    float2 in[8];
    #pragma unroll
    for (int a = 0; a < 8; a++) in[a] = nb[a * 8];

    const float2* sp = isp ? ((const float2*)pilot_raw + blk * 64)
                           : ((const float2*)x + ((size_t)blk * SS + (sym - 1)) * 64);
    float2 sv[8];
    #pragma unroll
    for (int d = 0; d < 8; d++) sv[d] = sp[lb + 8 * d];

    const float2* hp = (const float2*)(out + HT_OFF) + blk * 64;
    float2 hv[8];
    #pragma unroll
    for (int d = 0; d < 8; d++) hv[d] = hp[lb + 8 * d];

    // ---- pilot normalization (branch-free; payload lanes compute, then ignore) ----
    float pw = 0.f;
    #pragma unroll
    for (int d = 0; d < 8; d++) pw += sv[d].x * sv[d].x + sv[d].y * sv[d].y;
    pw += __shfl_xor_sync(0xffffffffu, pw, 1);
    pw += __shfl_xor_sync(0xffffffffu, pw, 2);
    pw += __shfl_xor_sync(0xffffffffu, pw, 4);
    float scale = isp ? 8.0f * rsqrtf(pw) : 1.0f;   // sqrt(64/pw) = sqrt(PWR/2)/sqrt(mean)
    #pragma unroll
    for (int d = 0; d < 8; d++) { sv[d].x *= scale; sv[d].y *= scale; }

    // ---- FFT64 of noise: stage 1 (DFT8 over a) + twiddle W64^{b*c} ----
    float2 u[8];
    dft8(in, u);
    #pragma unroll
    for (int c = 1; c < 8; c++) u[c] = cmul(u[c], sW[(lb * c) & 63]);

    // ---- 8x8 register transpose within each 8-lane group (xor-block) ----
    #pragma unroll
    for (int m = 1; m < 8; m <<= 1) {
        #pragma unroll
        for (int j = 0; j < 8; j++) {
            if ((j & m) == 0) {
                const int k = j | m;
                const bool up = (lb & m) != 0;
                float2 send = up ? u[j] : u[k];
                float2 recv;
                recv.x = __shfl_xor_sync(0xffffffffu, send.x, m);
                recv.y = __shfl_xor_sync(0xffffffffu, send.y, m);
                if (up) u[j] = recv; else u[k] = recv;
            }
        }
    }

    // ---- stage 2: DFT8 over b -> Nf[d] = N[lb + 8d] ----
    float2 Nf[8];
    dft8(u, Nf);

    // ---- fused epilogue: out = H * sig + CNOISE * noiseFFT ----
    float2* op = isp ? ((float2*)(out + IP_OFF) + blk * 64)
                     : ((float2*)(out + IS_OFF) + ((size_t)blk * SS + (sym - 1)) * 64);
    #pragma unroll
    for (int d = 0; d < 8; d++) {
        float2 r = cmul(hv[d], sv[d]);
        r.x = fmaf(CNOISE, Nf[d].x, r.x);
        r.y = fmaf(CNOISE, Nf[d].y, r.y);
        op[lb + 8 * d] = r;
    }
}

extern "C" void kernel_launch(void* const* d_in, const int* in_sizes, int n_in,
                              void* d_out, int out_size) {
    const float* x          = (const float*)d_in[0];
    const float* pilot_raw  = (const float*)d_in[1];
    const float* cof_unit   = (const float*)d_in[2];
    const float* noise_unit = (const float*)d_in[3];
    float* out = (float*)d_out;

    // K1: 4096 blk * 64 m = 262144 threads
    ofdm_k1<<<NBLK * 64 / 256, 256>>>(cof_unit, out);
    // K2: 53248 symbols * 8 threads = 425984 threads
    ofdm_k2<<<NSYMTOT * 8 / 256, 256>>>(x, pilot_raw, noise_unit, out);
}

// round 4
// speedup vs baseline: 1.3589x; 1.1196x over previous
#include <cuda_runtime.h>

// Problem constants
#define NN   1024
#define PP   4
#define SS   12
#define MM   64
#define KK   16
#define MK   80
#define NSYM 13
#define NBLK (NN*PP)              // 4096
#define NSYMTOT (NBLK*NSYM)       // 53248

// Output layout: [info_pilot | info_sig | H_true | noise_pwr]
#define IP_OFF 0
#define IS_OFF (NN*PP*MM*2)                  //   524288
#define HT_OFF (IS_OFF + NN*PP*SS*MM*2)      //  6815744
#define NP_OFF (HT_OFF + NN*PP*MM*2)         //  7340032

#define NOISE_PWR 1.5625e-4f                 // 1/(64*10^2)
#define CNOISE 8.8388347648e-3f              // sqrt(noise_pwr/2)
#define SQ2H 0.70710678f

// W64^k = exp(-2*pi*i*k/64)
__device__ const float2 g_W64[64] = {
    { 1.00000000f,  0.00000000f}, { 0.99518473f, -0.09801714f},
    { 0.98078528f, -0.19509032f}, { 0.95694034f, -0.29028468f},
    { 0.92387953f, -0.38268343f}, { 0.88192126f, -0.47139674f},
    { 0.83146961f, -0.55557023f}, { 0.77301045f, -0.63439328f},
    { 0.70710678f, -0.70710678f}, { 0.63439328f, -0.77301045f},
    { 0.55557023f, -0.83146961f}, { 0.47139674f, -0.88192126f},
    { 0.38268343f, -0.92387953f}, { 0.29028468f, -0.95694034f},
    { 0.19509032f, -0.98078528f}, { 0.09801714f, -0.99518473f},
    { 0.00000000f, -1.00000000f}, {-0.09801714f, -0.99518473f},
    {-0.19509032f, -0.98078528f}, {-0.29028468f, -0.95694034f},
    {-0.38268343f, -0.92387953f}, {-0.47139674f, -0.88192126f},
    {-0.55557023f, -0.83146961f}, {-0.63439328f, -0.77301045f},
    {-0.70710678f, -0.70710678f}, {-0.77301045f, -0.63439328f},
    {-0.83146961f, -0.55557023f}, {-0.88192126f, -0.47139674f},
    {-0.92387953f, -0.38268343f}, {-0.95694034f, -0.29028468f},
    {-0.98078528f, -0.19509032f}, {-0.99518473f, -0.09801714f},
    {-1.00000000f,  0.00000000f}, {-0.99518473f,  0.09801714f},
    {-0.98078528f,  0.19509032f}, {-0.95694034f,  0.29028468f},
    {-0.92387953f,  0.38268343f}, {-0.88192126f,  0.47139674f},
    {-0.83146961f,  0.55557023f}, {-0.77301045f,  0.63439328f},
    {-0.70710678f,  0.70710678f}, {-0.63439328f,  0.77301045f},
    {-0.55557023f,  0.83146961f}, {-0.47139674f,  0.88192126f},
    {-0.38268343f,  0.92387953f}, {-0.29028468f,  0.95694034f},
    {-0.19509032f,  0.98078528f}, {-0.09801714f,  0.99518473f},
    { 0.00000000f,  1.00000000f}, { 0.09801714f,  0.99518473f},
    { 0.19509032f,  0.98078528f}, { 0.29028468f,  0.95694034f},
    { 0.38268343f,  0.92387953f}, { 0.47139674f,  0.88192126f},
    { 0.55557023f,  0.83146961f}, { 0.63439328f,  0.77301045f},
    { 0.70710678f,  0.70710678f}, { 0.77301045f,  0.63439328f},
    { 0.83146961f,  0.55557023f}, { 0.88192126f,  0.47139674f},
    { 0.92387953f,  0.38268343f}, { 0.95694034f,  0.29028468f},
    { 0.98078528f,  0.19509032f}, { 0.99518473f,  0.09801714f}
};

// amp[l] = sqrt(0.5 * exp(-l/4) / sum_l exp(-l/4))   (compile-time constants)
__device__ const float g_amp[8] = {
    0.35764563f, 0.31562116f, 0.27853470f, 0.24580602f,
    0.21692305f, 0.19143393f, 0.16893985f, 0.14908891f
};

__device__ __forceinline__ float2 cadd(float2 a, float2 b) { return make_float2(a.x+b.x, a.y+b.y); }
__device__ __forceinline__ float2 csub(float2 a, float2 b) { return make_float2(a.x-b.x, a.y-b.y); }
__device__ __forceinline__ float2 mul_mi(float2 z) { return make_float2(z.y, -z.x); }   // -i*z
__device__ __forceinline__ float2 cmul(float2 a, float2 b) {
    return make_float2(a.x*b.x - a.y*b.y, a.x*b.y + a.y*b.x);
}
__device__ __forceinline__ float2 w81(float2 z) { return make_float2(SQ2H*(z.x+z.y), SQ2H*(z.y-z.x)); }
__device__ __forceinline__ float2 w83(float2 z) { return make_float2(SQ2H*(z.y-z.x), -SQ2H*(z.x+z.y)); }

// X[k] = sum_n x[n] * W8^{nk}  (radix-2 DIT)
__device__ __forceinline__ void dft8(const float2* x, float2* X) {
    float2 t0 = cadd(x[0], x[4]), t1 = csub(x[0], x[4]);
    float2 t2 = cadd(x[2], x[6]), t3 = csub(x[2], x[6]);
    float2 E0 = cadd(t0, t2), E2 = csub(t0, t2);
    float2 mt3 = mul_mi(t3);
    float2 E1 = cadd(t1, mt3), E3 = csub(t1, mt3);

    float2 s0 = cadd(x[1], x[5]), s1 = csub(x[1], x[5]);
    float2 s2 = cadd(x[3], x[7]), s3 = csub(x[3], x[7]);
    float2 O0 = cadd(s0, s2), O2 = csub(s0, s2);
    float2 ms3 = mul_mi(s3);
    float2 O1 = cadd(s1, ms3), O3 = csub(s1, ms3);

    float2 o1 = w81(O1);
    float2 o2 = mul_mi(O2);
    float2 o3 = w83(O3);

    X[0] = cadd(E0, O0); X[4] = csub(E0, O0);
    X[1] = cadd(E1, o1); X[5] = csub(E1, o1);
    X[2] = cadd(E2, o2); X[6] = csub(E2, o2);
    X[3] = cadd(E3, o3); X[7] = csub(E3, o3);
}

// 8x8 transpose across the 8-lane group (xor-block butterfly), in-place on v[8]
__device__ __forceinline__ void xpose8(float2* v, int lb) {
    #pragma unroll
    for (int m = 1; m < 8; m <<= 1) {
        #pragma unroll
        for (int j = 0; j < 8; j++) {
            if ((j & m) == 0) {
                const int k = j | m;
                const bool up = (lb & m) != 0;
                float2 send = up ? v[j] : v[k];
                float2 recv;
                recv.x = __shfl_xor_sync(0xffffffffu, send.x, m);
                recv.y = __shfl_xor_sync(0xffffffffu, send.y, m);
                if (up) v[j] = recv; else v[k] = recv;
            }
        }
    }
}

__global__ __launch_bounds__(128, 9) void ofdm_fused(
    const float* __restrict__ x,
    const float* __restrict__ pilot_raw,
    const float* __restrict__ cof_unit,
    const float* __restrict__ noise_unit,
    float* __restrict__ out)
{
    __shared__ float2 sW[64];
    const int tid = threadIdx.x;
    if (tid < 64) sW[tid] = g_W64[tid];
    __syncthreads();

    const int g    = blockIdx.x * 128 + tid;
    const int gsym = g >> 3;                  // 0..53247
    const int lb   = g & 7;
    const int blk  = gsym / NSYM;
    const int sym  = gsym - blk * NSYM;
    const bool isp = (sym == 0);

    // ---- global loads for the FFT phase ----
    float2 cu = ((const float2*)cof_unit)[blk * 8 + lb];
    const float amp = g_amp[lb];
    float2 cf = make_float2(amp * cu.x, amp * cu.y);

    const float2* nb = (const float2*)noise_unit
                     + (size_t)blk * NSYM * MK + sym * MK + KK + lb;
    float2 in[8];
    #pragma unroll
    for (int a = 0; a < 8; a++) in[a] = nb[a * 8];

    // ---- H = FFT64 of 8 taps (degenerate stage 1: only a=0 class) ----
    float2 uh[8];
    uh[0] = cf;
    #pragma unroll
    for (int c = 1; c < 8; c++) uh[c] = cmul(cf, sW[(lb * c) & 63]);
    xpose8(uh, lb);
    float2 Hv[8];
    dft8(uh, Hv);                             // Hv[d] = H[lb + 8d]

    // ---- noise FFT64: DFT8 + twiddle + transpose + DFT8 ----
    float2 u[8];
    dft8(in, u);
    #pragma unroll
    for (int c = 1; c < 8; c++) u[c] = cmul(u[c], sW[(lb * c) & 63]);
    xpose8(u, lb);
    float2 Nf[8];
    dft8(u, Nf);                              // Nf[d] = N[lb + 8d]

    // ---- sym-0 group owns H_true (+ noise_pwr) output ----
    if (isp) {
        float2* hq = (float2*)(out + HT_OFF) + blk * 64;
        #pragma unroll
        for (int d = 0; d < 8; d++) hq[lb + 8 * d] = Hv[d];
    }
    if (g == 0) out[NP_OFF] = NOISE_PWR;

    // ---- epilogue: load signal, scale pilot, combine, store ----
    const float2* sp = isp ? ((const float2*)pilot_raw + blk * 64)
                           : ((const float2*)x + ((size_t)blk * SS + (sym - 1)) * 64);
    float2 sv[8];
    #pragma unroll
    for (int d = 0; d < 8; d++) sv[d] = sp[lb + 8 * d];

    if (isp) {
        float pw = 0.f;
        #pragma unroll
        for (int d = 0; d < 8; d++) pw += sv[d].x * sv[d].x + sv[d].y * sv[d].y;
        pw += __shfl_xor_sync(0xffffffffu, pw, 1);
        pw += __shfl_xor_sync(0xffffffffu, pw, 2);
        pw += __shfl_xor_sync(0xffffffffu, pw, 4);
        float scale = 8.0f * rsqrtf(pw);      // sqrt(PWR/2)/sqrt(mean(pilot^2))
        #pragma unroll
        for (int d = 0; d < 8; d++) { sv[d].x *= scale; sv[d].y *= scale; }
    }

    float2* op = isp ? ((float2*)(out + IP_OFF) + blk * 64)
                     : ((float2*)(out + IS_OFF) + ((size_t)blk * SS + (sym - 1)) * 64);
    #pragma unroll
    for (int d = 0; d < 8; d++) {
        float2 r = cmul(Hv[d], sv[d]);
        r.x = fmaf(CNOISE, Nf[d].x, r.x);
        r.y = fmaf(CNOISE, Nf[d].y, r.y);
        op[lb + 8 * d] = r;
    }
}

extern "C" void kernel_launch(void* const* d_in, const int* in_sizes, int n_in,
                              void* d_out, int out_size) {
    const float* x          = (const float*)d_in[0];
    const float* pilot_raw  = (const float*)d_in[1];
    const float* cof_unit   = (const float*)d_in[2];
    const float* noise_unit = (const float*)d_in[3];
    float* out = (float*)d_out;

    // 53248 symbols * 8 threads = 425984 threads, 128/block -> 3328 blocks
    ofdm_fused<<<NSYMTOT * 8 / 128, 128>>>(x, pilot_raw, cof_unit, noise_unit, out);
}

// round 5
// speedup vs baseline: 1.5468x; 1.1383x over previous
#include <cuda_runtime.h>

// Problem constants
#define NN   1024
#define PP   4
#define SS   12
#define MM   64
#define KK   16
#define MK   80
#define NSYM 13
#define NBLK (NN*PP)              // 4096
#define NSYMTOT (NBLK*NSYM)       // 53248

// Output layout: [info_pilot | info_sig | H_true | noise_pwr]
#define IP_OFF 0
#define IS_OFF (NN*PP*MM*2)                  //   524288
#define HT_OFF (IS_OFF + NN*PP*SS*MM*2)      //  6815744
#define NP_OFF (HT_OFF + NN*PP*MM*2)         //  7340032

#define NOISE_PWR 1.5625e-4f                 // 1/(64*10^2)
#define CNOISE 8.8388347648e-3f              // sqrt(noise_pwr/2)
#define SQ2H 0.70710678f

// W64^j for j = 0..7  (all we need; higher powers come from the chain)
__constant__ float2 c_W8[8] = {
    { 1.00000000f,  0.00000000f}, { 0.99518473f, -0.09801714f},
    { 0.98078528f, -0.19509032f}, { 0.95694034f, -0.29028468f},
    { 0.92387953f, -0.38268343f}, { 0.88192126f, -0.47139674f},
    { 0.83146961f, -0.55557023f}, { 0.77301045f, -0.63439328f}
};

// amp[l] = sqrt(0.5 * exp(-l/4) / sum_l exp(-l/4))
__constant__ float c_amp[8] = {
    0.35764563f, 0.31562116f, 0.27853470f, 0.24580602f,
    0.21692305f, 0.19143393f, 0.16893985f, 0.14908891f
};

__device__ __forceinline__ float2 cadd(float2 a, float2 b) { return make_float2(a.x+b.x, a.y+b.y); }
__device__ __forceinline__ float2 csub(float2 a, float2 b) { return make_float2(a.x-b.x, a.y-b.y); }
__device__ __forceinline__ float2 mul_mi(float2 z) { return make_float2(z.y, -z.x); }   // -i*z
__device__ __forceinline__ float2 cmul(float2 a, float2 b) {
    return make_float2(fmaf(a.x, b.x, -a.y*b.y), fmaf(a.x, b.y, a.y*b.x));
}
__device__ __forceinline__ float2 w81(float2 z) { return make_float2(SQ2H*(z.x+z.y), SQ2H*(z.y-z.x)); }
__device__ __forceinline__ float2 w83(float2 z) { return make_float2(SQ2H*(z.y-z.x), -SQ2H*(z.x+z.y)); }

// X[k] = sum_n x[n] * W8^{nk}  (radix-2 DIT)
__device__ __forceinline__ void dft8(const float2* x, float2* X) {
    float2 t0 = cadd(x[0], x[4]), t1 = csub(x[0], x[4]);
    float2 t2 = cadd(x[2], x[6]), t3 = csub(x[2], x[6]);
    float2 E0 = cadd(t0, t2), E2 = csub(t0, t2);
    float2 mt3 = mul_mi(t3);
    float2 E1 = cadd(t1, mt3), E3 = csub(t1, mt3);

    float2 s0 = cadd(x[1], x[5]), s1 = csub(x[1], x[5]);
    float2 s2 = cadd(x[3], x[7]), s3 = csub(x[3], x[7]);
    float2 O0 = cadd(s0, s2), O2 = csub(s0, s2);
    float2 ms3 = mul_mi(s3);
    float2 O1 = cadd(s1, ms3), O3 = csub(s1, ms3);

    float2 o1 = w81(O1);
    float2 o2 = mul_mi(O2);
    float2 o3 = w83(O3);

    X[0] = cadd(E0, O0); X[4] = csub(E0, O0);
    X[1] = cadd(E1, o1); X[5] = csub(E1, o1);
    X[2] = cadd(E2, o2); X[6] = csub(E2, o2);
    X[3] = cadd(E3, o3); X[7] = csub(E3, o3);
}

__global__ __launch_bounds__(128, 8) void ofdm_fused(
    const float* __restrict__ x,
    const float* __restrict__ pilot_raw,
    const float* __restrict__ cof_unit,
    const float* __restrict__ noise_unit,
    float* __restrict__ out)
{
    // conflict-free transpose buffer: per half-warp phase all 16 lanes hit
    // distinct bytes mod 128 for both the write (stride 72B) and read patterns
    __shared__ float2 Z[16][8][9];

    const int tid  = threadIdx.x;
    const int g    = blockIdx.x * 128 + tid;
    const int gsym = g >> 3;                  // 0..53247
    const int lb   = g & 7;
    const int grp  = tid >> 3;
    const int blk  = gsym / NSYM;
    const int sym  = gsym - blk * NSYM;
    const bool isp = (sym == 0);

    // ---- noise loads (post-CP samples only), issued first for MLP ----
    const float2* nb = (const float2*)noise_unit
                     + (size_t)blk * NSYM * MK + sym * MK + KK + lb;
    float2 in[8];
    #pragma unroll
    for (int a = 0; a < 8; a++) in[a] = nb[a * 8];

    // ---- powers p[c] = W64^{lb*c}, log-depth chain from one constant ----
    float2 p1 = c_W8[lb];
    float2 p2 = cmul(p1, p1);
    float2 p3 = cmul(p2, p1);
    float2 p4 = cmul(p2, p2);
    float2 p5 = cmul(p4, p1);
    float2 p6 = cmul(p3, p3);
    float2 p7 = cmul(p4, p3);

    // ---- noise FFT64 stage 1: DFT8 over a, then twiddle W64^{lb*c} ----
    float2 u[8];
    dft8(in, u);
    u[1] = cmul(u[1], p1); u[2] = cmul(u[2], p2); u[3] = cmul(u[3], p3);
    u[4] = cmul(u[4], p4); u[5] = cmul(u[5], p5); u[6] = cmul(u[6], p6);
    u[7] = cmul(u[7], p7);
    #pragma unroll
    for (int c = 0; c < 8; c++) Z[grp][lb][c] = u[c];

    // ---- H in-thread (no transpose): Hv[d] = DFT8_l( amp_l*cof_l*W64^{l*lb} ) ----
    const float2* cp = (const float2*)cof_unit + blk * 8;   // broadcast within group
    float2 e[8];
    {
        float2 cv;
        cv = cp[0]; e[0] = make_float2(c_amp[0]*cv.x, c_amp[0]*cv.y);
        cv = cp[1]; cv = make_float2(c_amp[1]*cv.x, c_amp[1]*cv.y); e[1] = cmul(cv, p1);
        cv = cp[2]; cv = make_float2(c_amp[2]*cv.x, c_amp[2]*cv.y); e[2] = cmul(cv, p2);
        cv = cp[3]; cv = make_float2(c_amp[3]*cv.x, c_amp[3]*cv.y); e[3] = cmul(cv, p3);
        cv = cp[4]; cv = make_float2(c_amp[4]*cv.x, c_amp[4]*cv.y); e[4] = cmul(cv, p4);
        cv = cp[5]; cv = make_float2(c_amp[5]*cv.x, c_amp[5]*cv.y); e[5] = cmul(cv, p5);
        cv = cp[6]; cv = make_float2(c_amp[6]*cv.x, c_amp[6]*cv.y); e[6] = cmul(cv, p6);
        cv = cp[7]; cv = make_float2(c_amp[7]*cv.x, c_amp[7]*cv.y); e[7] = cmul(cv, p7);
    }
    float2 Hv[8];
    dft8(e, Hv);                              // Hv[d] = H[lb + 8d]

    // ---- signal loads overlap the transpose sync ----
    const float2* sp = isp ? ((const float2*)pilot_raw + blk * 64)
                           : ((const float2*)x + ((size_t)blk * SS + (sym - 1)) * 64);
    float2 sv[8];
    #pragma unroll
    for (int d = 0; d < 8; d++) sv[d] = sp[lb + 8 * d];

    __syncwarp();

    // ---- transpose read + stage 2 ----
    float2 z[8];
    #pragma unroll
    for (int b = 0; b < 8; b++) z[b] = Z[grp][b][lb];
    float2 Nf[8];
    dft8(z, Nf);                              // Nf[d] = N[lb + 8d]

    // ---- sym-0 group owns H_true (+ noise_pwr) ----
    if (isp) {
        float2* hq = (float2*)(out + HT_OFF) + blk * 64;
        #pragma unroll
        for (int d = 0; d < 8; d++) hq[lb + 8 * d] = Hv[d];

        // pilot normalization: scale = sqrt(PWR/2)/sqrt(mean(pilot_raw^2))
        float pw = 0.f;
        #pragma unroll
        for (int d = 0; d < 8; d++) pw += sv[d].x * sv[d].x + sv[d].y * sv[d].y;
        pw += __shfl_xor_sync(0xffffffffu, pw, 1);
        pw += __shfl_xor_sync(0xffffffffu, pw, 2);
        pw += __shfl_xor_sync(0xffffffffu, pw, 4);
        float scale = 8.0f * rsqrtf(pw);
        #pragma unroll
        for (int d = 0; d < 8; d++) { sv[d].x *= scale; sv[d].y *= scale; }
    }
    if (g == 0) out[NP_OFF] = NOISE_PWR;

    // ---- epilogue: out = H * sig + CNOISE * noiseFFT ----
    float2* op = isp ? ((float2*)(out + IP_OFF) + blk * 64)
                     : ((float2*)(out + IS_OFF) + ((size_t)blk * SS + (sym - 1)) * 64);
    #pragma unroll
    for (int d = 0; d < 8; d++) {
        float2 r = cmul(Hv[d], sv[d]);
        r.x = fmaf(CNOISE, Nf[d].x, r.x);
        r.y = fmaf(CNOISE, Nf[d].y, r.y);
        op[lb + 8 * d] = r;
    }
}

extern "C" void kernel_launch(void* const* d_in, const int* in_sizes, int n_in,
                              void* d_out, int out_size) {
    const float* x          = (const float*)d_in[0];
    const float* pilot_raw  = (const float*)d_in[1];
    const float* cof_unit   = (const float*)d_in[2];
    const float* noise_unit = (const float*)d_in[3];
    float* out = (float*)d_out;

    ofdm_fused<<<NSYMTOT * 8 / 128, 128>>>(x, pilot_raw, cof_unit, noise_unit, out);
}